// round 11
// baseline (speedup 1.0000x reference)
#include <cuda_runtime.h>
#include <cstdint>

#define NU    100000
#define NI    50000
#define NN    150000            // NU + NI
#define D     64
#define NNZ_  8000000
#define HOPS  3

// Static device scratch (per harness rules: no allocations).
__device__ int  g_cnt[NN];        // per-row edge count
__device__ int  g_start[NN];      // CSR row start
__device__ int  g_cursor[NN];     // scatter cursor
__device__ int2 g_edges[NNZ_];    // {col | keepmask<<18, val*2 bits}

// ---------------------------------------------------------------------------
// Init: out[:, 0, :] = concat(user, item)  (4 x float4 per thread, MLP=8)
//       + zero the row-count histogram.
// ---------------------------------------------------------------------------
__global__ void init_kernel(const float* __restrict__ user,
                            const float* __restrict__ item,
                            float* __restrict__ out) {
    int t = blockIdx.x * blockDim.x + threadIdx.x;
    if (t < NN) g_cnt[t] = 0;
    const int total = NN * D / 16;          // 600,000 threads
    if (t >= total) return;
    const int base   = t * 4;               // float4 index, aligned to 4
    const int userF4 = NU * D / 4;
    float4 v[4];
    #pragma unroll
    for (int i = 0; i < 4; ++i) {
        int idx = base + i;
        v[i] = (idx < userF4) ? ((const float4*)user)[idx]
                              : ((const float4*)item)[idx - userF4];
    }
    const int node = base >> 4;             // 16 float4 per node
    const int f4   = base & 15;
    #pragma unroll
    for (int i = 0; i < 4; ++i)
        ((float4*)out)[(size_t)node * 64 + f4 + i] = v[i];
}

// ---------------------------------------------------------------------------
// Histogram: g_cnt[rows[e]]++  — 4 independent edges per iteration (MLP).
// ---------------------------------------------------------------------------
__global__ void hist_kernel(const int* __restrict__ rows) {
    int t  = blockIdx.x * blockDim.x + threadIdx.x;
    int nt = gridDim.x * blockDim.x;
    for (int base = t; base < NNZ_; base += 4 * nt) {
        int e0 = base, e1 = base + nt, e2 = base + 2 * nt, e3 = base + 3 * nt;
        int r0 = 0, r1 = 0, r2 = 0, r3 = 0;
        if (e0 < NNZ_) r0 = __ldcs(rows + e0);
        if (e1 < NNZ_) r1 = __ldcs(rows + e1);
        if (e2 < NNZ_) r2 = __ldcs(rows + e2);
        if (e3 < NNZ_) r3 = __ldcs(rows + e3);
        if (e0 < NNZ_) atomicAdd(&g_cnt[r0], 1);
        if (e1 < NNZ_) atomicAdd(&g_cnt[r1], 1);
        if (e2 < NNZ_) atomicAdd(&g_cnt[r2], 1);
        if (e3 < NNZ_) atomicAdd(&g_cnt[r3], 1);
    }
}

// ---------------------------------------------------------------------------
// Exclusive scan of g_cnt -> g_start, g_cursor. One block, 1024 threads.
// ---------------------------------------------------------------------------
__global__ void scan_kernel() {
    const int T = 1024;
    const int C = (NN + T - 1) / T;         // 147 rows per thread
    int t = threadIdx.x;
    int s = 0;
    for (int i = 0; i < C; ++i) {
        int r = t * C + i;
        if (r < NN) s += g_cnt[r];
    }
    int lane = t & 31, w = t >> 5;
    int v = s;
    #pragma unroll
    for (int o = 1; o < 32; o <<= 1) {
        int n = __shfl_up_sync(0xFFFFFFFFu, v, o);
        if (lane >= o) v += n;
    }
    __shared__ int ws[32];
    if (lane == 31) ws[w] = v;
    __syncthreads();
    if (w == 0) {
        int x = ws[lane];
        #pragma unroll
        for (int o = 1; o < 32; o <<= 1) {
            int n = __shfl_up_sync(0xFFFFFFFFu, x, o);
            if (lane >= o) x += n;
        }
        ws[lane] = x;
    }
    __syncthreads();
    int run = v - s + (w > 0 ? ws[w - 1] : 0);   // exclusive prefix for this thread
    for (int i = 0; i < C; ++i) {
        int r = t * C + i;
        if (r < NN) {
            g_start[r]  = run;
            g_cursor[r] = run;
            run += g_cnt[r];
        }
    }
}

// ---------------------------------------------------------------------------
// Scatter edges into CSR order (4 independent edges/iteration for MLP).
// Record packs {col | keepmask<<18, val*2} — 8B, halves edge traffic.
// ---------------------------------------------------------------------------
__global__ void scatter_kernel(const int*   __restrict__ rows,
                               const int*   __restrict__ cols,
                               const float* __restrict__ vals,
                               const float* __restrict__ erand) {
    int t  = blockIdx.x * blockDim.x + threadIdx.x;
    int nt = gridDim.x * blockDim.x;
    for (int base = t; base < NNZ_; base += 4 * nt) {
        int  e[4];  bool g[4];
        int  r[4], p[4];  int2 rec[4];
        #pragma unroll
        for (int k = 0; k < 4; ++k) { e[k] = base + k * nt; g[k] = e[k] < NNZ_; }
        #pragma unroll
        for (int k = 0; k < 4; ++k) {
            if (g[k]) {
                int   ee = e[k];
                r[k]     = __ldcs(rows + ee);
                int   c  = __ldcs(cols + ee);
                float v  = __ldcs(vals + ee) * 2.0f;   // 1/(1-0.5)
                int m = (__ldcs(erand + ee)            >= 0.5f ? 1 : 0)
                      | (__ldcs(erand + NNZ_ + ee)     >= 0.5f ? 2 : 0)
                      | (__ldcs(erand + 2 * NNZ_ + ee) >= 0.5f ? 4 : 0);
                rec[k] = make_int2(c | (m << 18), __float_as_int(v));
            }
        }
        #pragma unroll
        for (int k = 0; k < 4; ++k)
            if (g[k]) p[k] = atomicAdd(&g_cursor[r[k]], 1);
        #pragma unroll
        for (int k = 0; k < 4; ++k)
            if (g[k]) g_edges[p[k]] = rec[k];
    }
}

// ---------------------------------------------------------------------------
// Fused CSR SpMM + message dropout. One warp per row, acc in registers
// (float2/lane over D=64). Warp stages 32 edge records to its smem slot with
// ONE coalesced load, then a fully-unrolled loop reads each record via
// LDS-broadcast and issues a PREDICATED float2 gather — no shuffles, no
// ballot, 32 independent gathers per chunk. Epilogue: message dropout +
// direct write of out[:, hop+1, :]. No atomics, no accumulator buffer.
// ---------------------------------------------------------------------------
__global__ void spmm_fused_kernel(const float* __restrict__ src,
                                  const float* __restrict__ mrand,
                                  float* __restrict__ out,
                                  int hop) {
    __shared__ int2 s_e[8][32];             // 8 warps x 32 records
    const int wib  = threadIdx.x >> 5;      // warp in block
    const int lane = threadIdx.x & 31;
    const int gw   = (blockIdx.x * blockDim.x + threadIdx.x) >> 5;
    const int nw   = (gridDim.x * blockDim.x) >> 5;
    const int hopbit = 1 << (18 + hop);

    for (int r = gw; r < NN; r += nw) {
        const int s = g_start[r];
        const int n = g_cnt[r];
        float accx = 0.f, accy = 0.f;
        for (int b = 0; b < n; b += 32) {
            int i = b + lane;
            int2 ed = (i < n) ? __ldcs(&g_edges[s + i]) : make_int2(0, 0);
            if (!(i < n)) ed.x = 0;          // mask bits clear -> skipped
            s_e[wib][lane] = ed;
            __syncwarp();
            const int lim = n - b;           // >=32 means full chunk
            #pragma unroll
            for (int j = 0; j < 32; ++j) {
                int2 e = s_e[wib][j];
                bool act = (j < lim) && (e.x & hopbit);
                if (act) {
                    int   c = e.x & 0x3FFFF;
                    float v = __int_as_float(e.y);
                    float2 x = __ldg((const float2*)(src + (size_t)c * 256) + lane);
                    accx += v * x.x;
                    accy += v * x.y;
                }
            }
            __syncwarp();
        }
        // fused message dropout + write next hop slice
        float2 m = __ldcs((const float2*)(mrand + (size_t)r * 64) + lane);
        const float sc = 1.0f / 0.9f;
        float2 o;
        o.x = (m.x >= 0.1f) ? accx * sc : 0.f;
        o.y = (m.y >= 0.1f) ? accy * sc : 0.f;
        *((float2*)(out + (size_t)r * 256 + (size_t)(hop + 1) * 64) + lane) = o;
    }
}

// ---------------------------------------------------------------------------
extern "C" void kernel_launch(void* const* d_in, const int* in_sizes, int n_in,
                              void* d_out, int out_size) {
    const float* user  = (const float*)d_in[0];
    const float* item  = (const float*)d_in[1];
    const int*   rows  = (const int*)  d_in[2];
    const int*   cols  = (const int*)  d_in[3];
    const float* vals  = (const float*)d_in[4];
    const float* erand = (const float*)d_in[5];
    const float* mrand = (const float*)d_in[6];
    float*       out   = (float*)d_out;

    const int totalT    = NN * D / 16;      // 600,000
    const int ewThreads = 256;
    const int ewBlocks  = (totalT + ewThreads - 1) / ewThreads;

    const int gsBlocks  = 148 * 32;         // grid-stride kernels
    const int gsThreads = 256;

    init_kernel<<<ewBlocks, ewThreads>>>(user, item, out);
    hist_kernel<<<gsBlocks, gsThreads>>>(rows);
    scan_kernel<<<1, 1024>>>();
    scatter_kernel<<<gsBlocks, gsThreads>>>(rows, cols, vals, erand);
    for (int hop = 0; hop < HOPS; ++hop) {
        spmm_fused_kernel<<<gsBlocks, gsThreads>>>(out + (size_t)hop * 64,
                                                   mrand + (size_t)hop * NN * D,
                                                   out, hop);
    }
}

// round 13
// speedup vs baseline: 1.4883x; 1.4883x over previous
#include <cuda_runtime.h>
#include <cstdint>

#define NU    100000
#define NI    50000
#define NN    150000            // NU + NI
#define D     64
#define NNZ_  8000000
#define HOPS  3

// SpMM accumulator (38.4 MB) — static __device__ per harness rules.
// The gather SOURCE is the out[:, hop, :] slice itself (no separate copy).
__device__ float g_bufB[(size_t)NN * D];

// L2 policy: keep hot buffers resident (evict_last).
__device__ __forceinline__ uint64_t evict_last_policy() {
    uint64_t pol;
    asm("createpolicy.fractional.L2::evict_last.b64 %0, 1.0;" : "=l"(pol));
    return pol;
}

__device__ __forceinline__ float4 ldg_evict_last_v4(const float4* p, uint64_t pol) {
    float4 x;
    asm("ld.global.nc.L2::cache_hint.v4.f32 {%0,%1,%2,%3}, [%4], %5;"
        : "=f"(x.x), "=f"(x.y), "=f"(x.z), "=f"(x.w)
        : "l"(p), "l"(pol));
    return x;
}

__device__ __forceinline__ void red_evict_last_v4(float* a, float4 x, uint64_t pol) {
    asm volatile("red.global.add.L2::cache_hint.v4.f32 [%0], {%1,%2,%3,%4}, %5;"
                 :: "l"(a), "f"(x.x), "f"(x.y), "f"(x.z), "f"(x.w), "l"(pol)
                 : "memory");
}

__device__ __forceinline__ void st_evict_last_v4(float4* p, float4 x, uint64_t pol) {
    asm volatile("st.global.L2::cache_hint.v4.f32 [%0], {%1,%2,%3,%4}, %5;"
                 :: "l"(p), "f"(x.x), "f"(x.y), "f"(x.z), "f"(x.w), "l"(pol)
                 : "memory");
}

// ---------------------------------------------------------------------------
// Init: out[:, 0, :] = concat(user, item); bufB = 0
// 4 float4 (64B) per thread: batched independent loads for latency hiding.
// ---------------------------------------------------------------------------
__global__ void init_kernel(const float* __restrict__ user,
                            const float* __restrict__ item,
                            float* __restrict__ out) {
    int t = blockIdx.x * blockDim.x + threadIdx.x;
    const int total = NN * D / 16;          // 600,000 threads
    if (t >= total) return;
    const uint64_t pol = evict_last_policy();
    const int base   = t * 4;               // float4 index, aligned to 4
    const int userF4 = NU * D / 4;
    float4 v[4];
    #pragma unroll
    for (int i = 0; i < 4; ++i) {
        int idx = base + i;
        v[i] = (idx < userF4) ? ((const float4*)user)[idx]
                              : ((const float4*)item)[idx - userF4];
    }
    #pragma unroll
    for (int i = 0; i < 4; ++i)
        ((float4*)g_bufB)[base + i] = make_float4(0.f, 0.f, 0.f, 0.f);
    const int node = base >> 4;             // 16 float4 per node
    const int f4   = base & 15;
    #pragma unroll
    for (int i = 0; i < 4; ++i)             // hop-0 slice: next spmm's gather source
        st_evict_last_v4((float4*)out + (size_t)node * 64 + f4 + i, v[i], pol);
}

// ---------------------------------------------------------------------------
// Edge-dropout SpMM: bufB[row] += 2*val * src[col] for kept edges (erand>=0.5)
// where src = out[:, hop, :] (node stride 256 floats, row = dense 256B).
// Edge streams: __ldcs (evict-first). Dense 16-lane x float4 layout.
// Per ballot-extraction: 8 kept edges, 4 per half-warp — FOUR independent
// gathers batched per lane before the four REDs (MLP=4).
// ---------------------------------------------------------------------------
__global__ void spmm_kernel(const int*   __restrict__ rows,
                            const int*   __restrict__ cols,
                            const float* __restrict__ vals,
                            const float* __restrict__ erand,
                            const float* __restrict__ src) {   // = out + hop*64
    const int gtid   = blockIdx.x * blockDim.x + threadIdx.x;
    const int warp   = gtid >> 5;
    const int lane   = gtid & 31;
    const int nwarps = (gridDim.x * blockDim.x) >> 5;
    const int sub    = lane & 15;          // position within half-warp (float4 idx)
    const bool hi    = lane >= 16;         // half-warp id

    const uint64_t pol = evict_last_policy();
    float* __restrict__ dst = g_bufB;

    for (int base = warp * 32; base < NNZ_; base += nwarps * 32) {
        int e = base + lane;
        bool inb  = (e < NNZ_);
        float u   = inb ? __ldcs(erand + e) : 0.f;
        bool keep = inb && (u >= 0.5f);
        float v = 0.f; int r = 0, c = 0;
        if (keep) {                          // only touch metadata for kept edges
            v = __ldcs(vals + e) * 2.0f;     // 1/(1-0.5)
            r = __ldcs(rows + e);
            c = __ldcs(cols + e);
        }
        unsigned mask = __ballot_sync(0xFFFFFFFFu, keep);
        while (mask) {
            // Extract up to 8 set bits (32 = "none").
            int l[8];
            #pragma unroll
            for (int k = 0; k < 8; ++k) {
                l[k] = mask ? (__ffs(mask) - 1) : 32;
                mask &= mask - 1;
            }
            // half 0 processes l0,l2,l4,l6 ; half 1 processes l1,l3,l5,l7
            int e0 = hi ? l[1] : l[0];
            int e1 = hi ? l[3] : l[2];
            int e2 = hi ? l[5] : l[4];
            int e3 = hi ? l[7] : l[6];
            bool a0 = e0 < 32, a1 = e1 < 32, a2 = e2 < 32, a3 = e3 < 32;
            int s0 = a0 ? e0 : 0, s1 = a1 ? e1 : 0, s2 = a2 ? e2 : 0, s3 = a3 ? e3 : 0;
            float v0 = __shfl_sync(0xFFFFFFFFu, v, s0);
            int   r0 = __shfl_sync(0xFFFFFFFFu, r, s0);
            int   c0 = __shfl_sync(0xFFFFFFFFu, c, s0);
            float v1 = __shfl_sync(0xFFFFFFFFu, v, s1);
            int   r1 = __shfl_sync(0xFFFFFFFFu, r, s1);
            int   c1 = __shfl_sync(0xFFFFFFFFu, c, s1);
            float v2 = __shfl_sync(0xFFFFFFFFu, v, s2);
            int   r2 = __shfl_sync(0xFFFFFFFFu, r, s2);
            int   c2 = __shfl_sync(0xFFFFFFFFu, c, s2);
            float v3 = __shfl_sync(0xFFFFFFFFu, v, s3);
            int   r3 = __shfl_sync(0xFFFFFFFFu, r, s3);
            int   c3 = __shfl_sync(0xFFFFFFFFu, c, s3);
            float4 x0, x1, x2, x3;
            if (a0) x0 = ldg_evict_last_v4((const float4*)(src + (size_t)c0 * 256) + sub, pol);
            if (a1) x1 = ldg_evict_last_v4((const float4*)(src + (size_t)c1 * 256) + sub, pol);
            if (a2) x2 = ldg_evict_last_v4((const float4*)(src + (size_t)c2 * 256) + sub, pol);
            if (a3) x3 = ldg_evict_last_v4((const float4*)(src + (size_t)c3 * 256) + sub, pol);
            if (a0) {
                x0.x *= v0; x0.y *= v0; x0.z *= v0; x0.w *= v0;
                red_evict_last_v4(dst + (size_t)r0 * D + sub * 4, x0, pol);
            }
            if (a1) {
                x1.x *= v1; x1.y *= v1; x1.z *= v1; x1.w *= v1;
                red_evict_last_v4(dst + (size_t)r1 * D + sub * 4, x1, pol);
            }
            if (a2) {
                x2.x *= v2; x2.y *= v2; x2.z *= v2; x2.w *= v2;
                red_evict_last_v4(dst + (size_t)r2 * D + sub * 4, x2, pol);
            }
            if (a3) {
                x3.x *= v3; x3.y *= v3; x3.z *= v3; x3.w *= v3;
                red_evict_last_v4(dst + (size_t)r3 * D + sub * 4, x3, pol);
            }
        }
    }
}

// ---------------------------------------------------------------------------
// Message dropout + epilogue: a = bufB * (mrand>=0.1) / 0.9
//   out[:, hop+1, :] = a (next hop's gather source) ; bufB = 0
// 4 float4 (64B) per thread: 8 independent loads in flight before compute.
// ---------------------------------------------------------------------------
__global__ void dropout_kernel(const float* __restrict__ mrand,
                               float* __restrict__ out,
                               int hop) {
    int t = blockIdx.x * blockDim.x + threadIdx.x;
    const int total = NN * D / 16;          // 600,000 threads
    if (t >= total) return;
    const uint64_t pol = evict_last_policy();
    const int base = t * 4;
    float4 a[4], m[4];
    #pragma unroll
    for (int i = 0; i < 4; ++i) a[i] = ((const float4*)g_bufB)[base + i];
    #pragma unroll
    for (int i = 0; i < 4; ++i) m[i] = __ldcs((const float4*)mrand + base + i);
    const float s = 1.0f / 0.9f;
    #pragma unroll
    for (int i = 0; i < 4; ++i) {
        a[i].x = (m[i].x >= 0.1f) ? a[i].x * s : 0.f;
        a[i].y = (m[i].y >= 0.1f) ? a[i].y * s : 0.f;
        a[i].z = (m[i].z >= 0.1f) ? a[i].z * s : 0.f;
        a[i].w = (m[i].w >= 0.1f) ? a[i].w * s : 0.f;
    }
    #pragma unroll
    for (int i = 0; i < 4; ++i)
        ((float4*)g_bufB)[base + i] = make_float4(0.f, 0.f, 0.f, 0.f);
    const int node = base >> 4;
    const int f4   = base & 15;
    float4* op = (float4*)out + (size_t)node * 64 + (size_t)(hop + 1) * 16 + f4;
    #pragma unroll
    for (int i = 0; i < 4; ++i)
        st_evict_last_v4(op + i, a[i], pol);
}

// ---------------------------------------------------------------------------
extern "C" void kernel_launch(void* const* d_in, const int* in_sizes, int n_in,
                              void* d_out, int out_size) {
    const float* user  = (const float*)d_in[0];
    const float* item  = (const float*)d_in[1];
    const int*   rows  = (const int*)  d_in[2];
    const int*   cols  = (const int*)  d_in[3];
    const float* vals  = (const float*)d_in[4];
    const float* erand = (const float*)d_in[5];
    const float* mrand = (const float*)d_in[6];
    float*       out   = (float*)d_out;

    const int totalT    = NN * D / 16;      // 600,000
    const int ewThreads = 256;
    const int ewBlocks  = (totalT + ewThreads - 1) / ewThreads;   // 2344

    const int spThreads = 256;
    const int spBlocks  = 148 * 32;                               // grid-stride

    // Launch order: 0 init, 1 spmm0, 2 drop0, 3 spmm1, 4 drop1, 5 spmm2 ...
    // ncu -s 5 -c 1 → profiles spmm hop 2.
    init_kernel<<<ewBlocks, ewThreads>>>(user, item, out);
    for (int hop = 0; hop < HOPS; ++hop) {
        spmm_kernel<<<spBlocks, spThreads>>>(rows, cols, vals,
                                             erand + (size_t)hop * NNZ_,
                                             out + (size_t)hop * 64);
        dropout_kernel<<<ewBlocks, ewThreads>>>(mrand + (size_t)hop * NN * D,
                                                out, hop);
    }
}